// round 13
// baseline (speedup 1.0000x reference)
#include <cuda_runtime.h>
#include <math.h>

#define BB 16
#define TT 32
#define PP 14
#define HH 12
#define DD 64
#define LL 196
#define DMODEL 768
#define SS 16

#define GMS 36               // gm row stride
#define GMH 1156             // gm head stride (=4 mod 32 banks, float4 aligned)
#define XS_HSTR 2178         // xsT head stride (=2 mod 32 banks)
#define XS_FLOATS (4 * XS_HSTR)                    // 8712
#define K1_SMEM ((XS_FLOATS + 4 * GMH) * 4)        // 53344 bytes

// ---------------- scratch (device globals; no allocation allowed) -------------
__device__ __align__(16) float g_aff0[(size_t)BB * LL * 1024];
__device__ __align__(16) float g_y1[(size_t)BB * LL * 1024];
__device__ __align__(16) float g_ypart[(size_t)BB * TT * DMODEL];

// triangular tile map: 36 tiles (i<=j) in an 8x8 tile grid
__constant__ int c_TI[36] = {0,0,0,0,0,0,0,0, 1,1,1,1,1,1,1, 2,2,2,2,2,2,
                             3,3,3,3,3, 4,4,4,4, 5,5,5, 6,6, 7};
__constant__ int c_TJ[36] = {0,1,2,3,4,5,6,7, 1,2,3,4,5,6,7, 2,3,4,5,6,7,
                             3,4,5,6,7, 4,5,6,7, 5,6,7, 6,7, 7};

// ---------------- f32x2 packed-FMA helpers (sm_10x) ---------------------------
__device__ __forceinline__ unsigned long long pk2(float lo, float hi) {
    unsigned long long r;
    asm("mov.b64 %0, {%1, %2};" : "=l"(r) : "f"(lo), "f"(hi));
    return r;
}
__device__ __forceinline__ void upk2(unsigned long long v, float& lo, float& hi) {
    asm("mov.b64 {%0, %1}, %2;" : "=f"(lo), "=f"(hi) : "l"(v));
}
__device__ __forceinline__ void fma2(unsigned long long& d, unsigned long long a,
                                     unsigned long long b) {
    asm("fma.rn.f32x2 %0, %1, %2, %0;" : "+l"(d) : "l"(a), "l"(b));
}

// =============================================================================
// Kernel 1: R11 structure; loader remapped to conflict-free STS
// (each warp covers two t values x 16 d -> banks span all 32).
// =============================================================================
__device__ __forceinline__ void k1_load_chunk(
    float* __restrict__ sm1, const float* __restrict__ qp,
    const float* __restrict__ kp, int b, int l, int chunk, int tid)
{
    const int lane = tid & 31;
    const int grp  = tid >> 5;                 // 0..7
    const int dlo  = lane & 15;
    const int thi  = lane >> 4;                // 0 or 1
    #pragma unroll
    for (int g = 0; g < 4; g++) {
        int c = chunk * 4 + g;
        const float* src = (c < HH) ? qp : kp;
        int h = c % HH;
        const float* base = src + ((size_t)b * TT * 197 + (l + 1)) * DMODEL + h * DD;
        #pragma unroll
        for (int j = 0; j < 8; j++) {
            int s = grp + j * 8;               // group 0..63
            int dblk = s & 3, tp = s >> 2;     // d block of 16, t pair 0..15
            int t = 2 * tp + thi;
            int d = dblk * 16 + dlo;
            sm1[g * XS_HSTR + d * 34 + t] =
                base[(size_t)t * 197 * DMODEL + d] * 0.35355339059327376f;
        }
    }
}

__global__ __launch_bounds__(256) void k1_gram(
    const float* __restrict__ qp, const float* __restrict__ kp,
    const float* __restrict__ tw, const float* __restrict__ tb)
{
    extern __shared__ __align__(16) float dsm[];
    float* sm1 = dsm;
    float* gm  = dsm + XS_FLOATS;

    const int tid = threadIdx.x;
    const int bl = blockIdx.x;
    const int b = bl / LL, l = bl % LL;

    const bool gact = (tid < 144);
    const int gj = gact ? (tid / 36) : 0;
    const int tt = gact ? (tid - gj * 36) : 0;
    const int ti = gact ? c_TI[tt] : 0;
    const int tj = gact ? c_TJ[tt] : 0;
    const int q0 = ti * 4, k0 = tj * 4;

    const int ct1 = tid >> 3, ct2 = (tid & 7) * 4;
    const int lc = tid & 7;

    float racc[4] = {0.f, 0.f, 0.f, 0.f};

    k1_load_chunk(sm1, qp, kp, b, l, 0, tid);

    for (int chunk = 0; chunk < 6; chunk++) {
        __syncthreads();

        {
            unsigned long long acc[4][2] = {{0ull,0ull},{0ull,0ull},{0ull,0ull},{0ull,0ull}};
            if (gact) {
                const float* xg = sm1 + gj * XS_HSTR;
                #pragma unroll 4
                for (int d = 0; d < 64; d++) {
                    const float* row = xg + d * 34;
                    unsigned long long qa = *(const unsigned long long*)(row + q0);
                    unsigned long long qb = *(const unsigned long long*)(row + q0 + 2);
                    unsigned long long kk0 = *(const unsigned long long*)(row + k0);
                    unsigned long long kk1 = *(const unsigned long long*)(row + k0 + 2);
                    float q0v, q1v, q2v, q3v;
                    upk2(qa, q0v, q1v); upk2(qb, q2v, q3v);
                    unsigned long long p0 = pk2(q0v, q0v), p1 = pk2(q1v, q1v);
                    unsigned long long p2 = pk2(q2v, q2v), p3 = pk2(q3v, q3v);
                    fma2(acc[0][0], p0, kk0); fma2(acc[0][1], p0, kk1);
                    fma2(acc[1][0], p1, kk0); fma2(acc[1][1], p1, kk1);
                    fma2(acc[2][0], p2, kk0); fma2(acc[2][1], p2, kk1);
                    fma2(acc[3][0], p3, kk0); fma2(acc[3][1], p3, kk1);
                }
                float* gmg = gm + gj * GMH;
                #pragma unroll
                for (int r = 0; r < 4; r++) {
                    *(unsigned long long*)&gmg[(q0 + r) * GMS + k0]     = acc[r][0];
                    *(unsigned long long*)&gmg[(q0 + r) * GMS + k0 + 2] = acc[r][1];
                }
                if (ti != tj) {
                    float av[4][4];
                    #pragma unroll
                    for (int r = 0; r < 4; r++) {
                        upk2(acc[r][0], av[r][0], av[r][1]);
                        upk2(acc[r][1], av[r][2], av[r][3]);
                    }
                    #pragma unroll
                    for (int c = 0; c < 4; c++)
                        #pragma unroll
                        for (int r = 0; r < 4; r++)
                            gmg[(k0 + c) * GMS + q0 + r] = av[r][c];
                }
            }
        }
        __syncthreads();

        if (chunk + 1 < 6) k1_load_chunk(sm1, qp, kp, b, l, chunk + 1, tid);

        {
            int r = tid >> 1, h = tid & 1;
            float* row = gm + (r >> 5) * GMH + (r & 31) * GMS + h * 16;
            float4 v[4];
            #pragma unroll
            for (int j = 0; j < 4; j++) v[j] = *(const float4*)&row[j * 4];
            float mx = -1e30f;
            #pragma unroll
            for (int j = 0; j < 4; j++)
                mx = fmaxf(mx, fmaxf(fmaxf(v[j].x, v[j].y), fmaxf(v[j].z, v[j].w)));
            mx = fmaxf(mx, __shfl_xor_sync(0xffffffffu, mx, 1));
            float sum = 0.f;
            #pragma unroll
            for (int j = 0; j < 4; j++) {
                v[j].x = __expf(v[j].x - mx); v[j].y = __expf(v[j].y - mx);
                v[j].z = __expf(v[j].z - mx); v[j].w = __expf(v[j].w - mx);
                sum += (v[j].x + v[j].y) + (v[j].z + v[j].w);
            }
            sum += __shfl_xor_sync(0xffffffffu, sum, 1);
            float inv = __fdividef(1.f, sum);
            #pragma unroll
            for (int j = 0; j < 4; j++) {
                v[j].x *= inv; v[j].y *= inv; v[j].z *= inv; v[j].w *= inv;
                *(float4*)&row[j * 4] = v[j];
            }
        }
        __syncthreads();

        {
            float wreg[4][9];
            #pragma unroll
            for (int g = 0; g < 4; g++)
                #pragma unroll
                for (int j = 0; j < 9; j++) wreg[g][j] = tw[(chunk * 4 + g) * 9 + j];
            #pragma unroll
            for (int g = 0; g < 4; g++) {
                const float* gg = gm + g * GMH;
                #pragma unroll
                for (int dy = 0; dy < 3; dy++) {
                    int y = ct1 + dy - 1;
                    bool vy = ((unsigned)y < 32u);
                    float4 mid = vy ? *(const float4*)&gg[y * GMS + ct2]
                                    : make_float4(0.f, 0.f, 0.f, 0.f);
                    float wl = __shfl_up_sync(0xffffffffu, mid.w, 1);
                    float wr = __shfl_down_sync(0xffffffffu, mid.x, 1);
                    if (lc == 0) wl = 0.f;
                    if (lc == 7) wr = 0.f;
                    float win[6] = {wl, mid.x, mid.y, mid.z, mid.w, wr};
                    #pragma unroll
                    for (int dx = 0; dx < 3; dx++) {
                        float wt = wreg[g][dy * 3 + dx];
                        #pragma unroll
                        for (int m = 0; m < 4; m++)
                            racc[m] = fmaf(win[m + dx], wt, racc[m]);
                    }
                }
            }
        }
    }

    float bias = tb[0];
    float4 o = make_float4(racc[0] + bias, racc[1] + bias, racc[2] + bias, racc[3] + bias);
    *(float4*)&g_aff0[(size_t)bl * 1024 + ct1 * 32 + ct2] = o;
}

// =============================================================================
// Kernel 2: LN + MLP + residual, 8 rows per block.  (unchanged)
// =============================================================================
__global__ __launch_bounds__(256) void k2_mlp(
    const float* __restrict__ lng, const float* __restrict__ lnb,
    const float* __restrict__ w1, const float* __restrict__ b1,
    const float* __restrict__ w2, const float* __restrict__ b2)
{
    __shared__ __align__(16) float xnT[1024 * 8];
    __shared__ float part[8 * 256];
    __shared__ float hs[256];
    __shared__ float mu[8], rs[8];

    const int tid = threadIdx.x;
    const int warp = tid >> 5, lane = tid & 31;
    const size_t R0 = (size_t)blockIdx.x * 8;

    {
        const float* xrow = g_aff0 + (R0 + warp) * 1024;
        float s1 = 0.f, s2 = 0.f;
        #pragma unroll 8
        for (int kk = 0; kk < 32; kk++) {
            float v = xrow[lane + 32 * kk];
            s1 += v; s2 += v * v;
        }
        #pragma unroll
        for (int o = 16; o > 0; o >>= 1) {
            s1 += __shfl_xor_sync(0xffffffffu, s1, o);
            s2 += __shfl_xor_sync(0xffffffffu, s2, o);
        }
        if (lane == 0) {
            float m = s1 * (1.f / 1024.f);
            float var = s2 * (1.f / 1024.f) - m * m;
            mu[warp] = m;
            rs[warp] = rsqrtf(var + 1e-5f);
        }
    }
    __syncthreads();

    for (int idx = tid; idx < 8192; idx += 256) {
        int r = idx >> 10, i = idx & 1023;
        float v = g_aff0[(R0 + r) * 1024 + i];
        xnT[i * 8 + r] = (v - mu[r]) * rs[r] * lng[i] + lnb[i];
    }
    __syncthreads();

    {
        unsigned long long acc[4] = {0ull, 0ull, 0ull, 0ull};
        int i0 = warp * 128;
        #pragma unroll 4
        for (int i = i0; i < i0 + 128; i++) {
            float wv = w1[i * 32 + lane];
            unsigned long long wp = pk2(wv, wv);
            const unsigned long long* xp = (const unsigned long long*)&xnT[i * 8];
            fma2(acc[0], wp, xp[0]);
            fma2(acc[1], wp, xp[1]);
            fma2(acc[2], wp, xp[2]);
            fma2(acc[3], wp, xp[3]);
        }
        #pragma unroll
        for (int rp = 0; rp < 4; rp++) {
            float a, bv; upk2(acc[rp], a, bv);
            part[warp * 256 + (2 * rp) * 32 + lane] = a;
            part[warp * 256 + (2 * rp + 1) * 32 + lane] = bv;
        }
    }
    __syncthreads();

    {
        float h = b1[lane];
        #pragma unroll
        for (int w = 0; w < 8; w++) h += part[w * 256 + warp * 32 + lane];
        hs[warp * 32 + lane] = 0.5f * h * (1.0f + erff(h * 0.70710678118654752f));
    }
    __syncthreads();

    #pragma unroll
    for (int u = 0; u < 4; u++) {
        int i = tid + u * 256;
        float acc[8];
        #pragma unroll
        for (int r = 0; r < 8; r++) acc[r] = g_aff0[(R0 + r) * 1024 + i];
        float bb = b2[i];
        #pragma unroll 8
        for (int j = 0; j < 32; j++) {
            float wv = w2[j * 1024 + i];
            #pragma unroll
            for (int r = 0; r < 8; r++) acc[r] = fmaf(hs[r * 32 + j], wv, acc[r]);
        }
        #pragma unroll
        for (int r = 0; r < 8; r++) g_y1[(R0 + r) * 1024 + i] = acc[r] + bb;
    }
}

// =============================================================================
// Kernel 3: p_conv 1024ch -> 1.  (unchanged)
// =============================================================================
__global__ __launch_bounds__(256) void k3_pconv(
    const float* __restrict__ pw, const float* __restrict__ pb,
    float* __restrict__ out)
{
    __shared__ float red[8];
    const int tid = threadIdx.x;
    const int bi = blockIdx.x;
    const int b = bi / LL, l = bi % LL;
    const int p1 = l / PP, p2 = l % PP;
    const int ch = tid * 4;

    float wreg[9][4];
    #pragma unroll
    for (int tap = 0; tap < 9; tap++)
        #pragma unroll
        for (int m = 0; m < 4; m++) wreg[tap][m] = pw[(ch + m) * 9 + tap];

    float4 a = make_float4(0.f, 0.f, 0.f, 0.f);
    #pragma unroll
    for (int dy = 0; dy < 3; dy++) {
        int y = p1 + dy - 1;
        if ((unsigned)y >= (unsigned)PP) continue;
        #pragma unroll
        for (int dx = 0; dx < 3; dx++) {
            int x = p2 + dx - 1;
            if ((unsigned)x >= (unsigned)PP) continue;
            const float4 row = *(const float4*)&g_y1[((size_t)b * LL + y * PP + x) * 1024 + ch];
            int tap = dy * 3 + dx;
            a.x = fmaf(row.x, wreg[tap][0], a.x);
            a.y = fmaf(row.y, wreg[tap][1], a.y);
            a.z = fmaf(row.z, wreg[tap][2], a.z);
            a.w = fmaf(row.w, wreg[tap][3], a.w);
        }
    }
    float s = a.x + a.y + a.z + a.w;
    #pragma unroll
    for (int o = 16; o > 0; o >>= 1) s += __shfl_xor_sync(0xffffffffu, s, o);
    if ((tid & 31) == 0) red[tid >> 5] = s;
    __syncthreads();
    if (tid == 0) {
        float t = pb[0];
        #pragma unroll
        for (int w = 0; w < 8; w++) t += red[w];
        out[bi] = t;
    }
}

// =============================================================================
// Kernel 4: spatial syno attention — REVERTED to the R9 form (measured 201us).
// =============================================================================
__global__ __launch_bounds__(256) void k4_spatial(
    const float* __restrict__ kp, const float* __restrict__ vp,
    const float* __restrict__ syno)
{
    __shared__ __align__(16) float buf[32 * 256];
    __shared__ __align__(16) float sc[16 * 200];
    __shared__ __align__(16) float syT[32 * 16];
    __shared__ float Pb[196];

    const int tid = threadIdx.x;
    const int bt = blockIdx.x;
    const float* kbase = kp + ((size_t)bt * 197 + 1) * DMODEL;
    const float* vbase = vp + ((size_t)bt * 197 + 1) * DMODEL;
    const float scale = 0.03608439182435161f;

    const int sg = tid / 49;
    const int lg = tid % 49;
    const bool act = (tid < 196);

    unsigned long long acc[4][2] = {{0ull,0ull},{0ull,0ull},{0ull,0ull},{0ull,0ull}};

    for (int dc = 0; dc < 24; dc++) {
        int d0 = dc * 32;
        if (tid < 128) {
            int s = tid >> 3, dq = tid & 7;
            float4 sv = *(const float4*)&syno[s * DMODEL + d0 + dq * 4];
            int base = 4 * ((s >> 2) ^ (dq & 3)) + (s & 3);
            syT[(dq * 4 + 0) * 16 + base] = sv.x * scale;
            syT[(dq * 4 + 1) * 16 + base] = sv.y * scale;
            syT[(dq * 4 + 2) * 16 + base] = sv.z * scale;
            syT[(dq * 4 + 3) * 16 + base] = sv.w * scale;
        }
        for (int idx = tid; idx < 1568; idx += 256) {
            int l = idx >> 3, kq = idx & 7;
            float4 kv = *(const float4*)&kbase[(size_t)l * DMODEL + d0 + kq * 4];
            int base = 4 * ((l >> 2) ^ kq) + (l & 3);
            buf[(kq * 4 + 0) * 256 + base] = kv.x;
            buf[(kq * 4 + 1) * 256 + base] = kv.y;
            buf[(kq * 4 + 2) * 256 + base] = kv.z;
            buf[(kq * 4 + 3) * 256 + base] = kv.w;
        }
        __syncthreads();
        if (act) {
            #pragma unroll 4
            for (int dd = 0; dd < 32; dd++) {
                float4 sa = *(const float4*)&syT[dd * 16 + 4 * (sg ^ ((dd >> 2) & 3))];
                float4 ka = *(const float4*)&buf[dd * 256 + 4 * (lg ^ ((dd >> 2) & 7))];
                unsigned long long k01 = pk2(ka.x, ka.y), k23 = pk2(ka.z, ka.w);
                unsigned long long s0 = pk2(sa.x, sa.x), s1 = pk2(sa.y, sa.y);
                unsigned long long s2 = pk2(sa.z, sa.z), s3 = pk2(sa.w, sa.w);
                fma2(acc[0][0], s0, k01); fma2(acc[0][1], s0, k23);
                fma2(acc[1][0], s1, k01); fma2(acc[1][1], s1, k23);
                fma2(acc[2][0], s2, k01); fma2(acc[2][1], s2, k23);
                fma2(acc[3][0], s3, k01); fma2(acc[3][1], s3, k23);
            }
        }
        __syncthreads();
    }
    if (act) {
        #pragma unroll
        for (int i = 0; i < 4; i++) {
            *(unsigned long long*)&sc[(sg * 4 + i) * 200 + lg * 4]     = acc[i][0];
            *(unsigned long long*)&sc[(sg * 4 + i) * 200 + lg * 4 + 2] = acc[i][1];
        }
    }
    __syncthreads();

    const int warp = tid >> 5, lane = tid & 31;
    #pragma unroll
    for (int si = 0; si < 2; si++) {
        int s = warp * 2 + si;
        float mx = -1e30f;
        for (int li = lane; li < 196; li += 32) mx = fmaxf(mx, sc[s * 200 + li]);
        #pragma unroll
        for (int o = 16; o > 0; o >>= 1) mx = fmaxf(mx, __shfl_xor_sync(0xffffffffu, mx, o));
        float sum = 0.f;
        for (int li = lane; li < 196; li += 32) {
            float e = __expf(sc[s * 200 + li] - mx);
            sc[s * 200 + li] = e; sum += e;
        }
        #pragma unroll
        for (int o = 16; o > 0; o >>= 1) sum += __shfl_xor_sync(0xffffffffu, sum, o);
        float inv = __fdividef(1.f, sum);
        for (int li = lane; li < 196; li += 32) sc[s * 200 + li] *= inv;
    }
    __syncthreads();

    if (tid < 196) {
        float p = 0.f;
        #pragma unroll
        for (int s = 0; s < 16; s++) p += sc[s * 200 + tid];
        Pb[tid] = p;
    }
    __syncthreads();

    if (tid < 192) {
        int w4 = tid * 4;
        float ax = 0.f, ay = 0.f, az = 0.f, aw = 0.f;
        for (int l = 0; l < 196; l += 4) {
            #pragma unroll
            for (int u = 0; u < 4; u++) {
                float p = Pb[l + u];
                float4 vv = *(const float4*)&vbase[(size_t)(l + u) * DMODEL + w4];
                ax = fmaf(p, vv.x, ax);
                ay = fmaf(p, vv.y, ay);
                az = fmaf(p, vv.z, az);
                aw = fmaf(p, vv.w, aw);
            }
        }
        *(float4*)&g_ypart[(size_t)bt * DMODEL + w4] = make_float4(ax, ay, az, aw);
    }
}

// =============================================================================
// Kernel 5: y_s[b][w] = sum_t partial / 512
// =============================================================================
__global__ __launch_bounds__(768) void k5_reduce(float* __restrict__ out)
{
    const int b = blockIdx.x, w = threadIdx.x;
    float s = 0.f;
    #pragma unroll
    for (int t = 0; t < 32; t++) s += g_ypart[((size_t)b * 32 + t) * DMODEL + w];
    out[b * DMODEL + w] = s * (1.f / 512.f);
}

// =============================================================================
extern "C" void kernel_launch(void* const* d_in, const int* in_sizes, int n_in,
                              void* d_out, int out_size)
{
    const float* q    = (const float*)d_in[0];
    const float* k    = (const float*)d_in[1];
    const float* v    = (const float*)d_in[2];
    const float* tw   = (const float*)d_in[3];
    const float* tb   = (const float*)d_in[4];
    const float* lng  = (const float*)d_in[5];
    const float* lnb  = (const float*)d_in[6];
    const float* w1   = (const float*)d_in[7];
    const float* b1   = (const float*)d_in[8];
    const float* w2   = (const float*)d_in[9];
    const float* b2   = (const float*)d_in[10];
    const float* pw   = (const float*)d_in[11];
    const float* pb   = (const float*)d_in[12];
    const float* syno = (const float*)d_in[13];
    float* out = (float*)d_out;

    static int s_attr_done = 0;
    if (!s_attr_done) {
        cudaFuncSetAttribute(k1_gram, cudaFuncAttributeMaxDynamicSharedMemorySize,
                             K1_SMEM);
        s_attr_done = 1;
    }

    k1_gram<<<BB * LL, 256, K1_SMEM>>>(q, k, tw, tb);
    k2_mlp<<<BB * LL / 8, 256>>>(lng, lnb, w1, b1, w2, b2);
    k3_pconv<<<BB * LL, 256>>>(pw, pb, out);
    k4_spatial<<<BB * TT, 256>>>(k, v, syno);
    k5_reduce<<<BB, 768>>>(out + BB * LL);
}

// round 14
// speedup vs baseline: 1.5001x; 1.5001x over previous
#include <cuda_runtime.h>
#include <math.h>

#define BB 16
#define TT 32
#define PP 14
#define HH 12
#define DD 64
#define LL 196
#define DMODEL 768
#define SS 16

#define GMS 36               // gm row stride
#define GMH 1156             // gm head stride (=4 mod 32 banks, float4 aligned)
#define XS_HSTR 2178         // xsT head stride (=2 mod 32 banks)
#define XS_FLOATS (4 * XS_HSTR)                    // 8712
#define K1_SMEM ((XS_FLOATS + 4 * GMH) * 4)        // 53344 bytes

// ---------------- scratch (device globals; no allocation allowed) -------------
__device__ __align__(16) float g_aff0[(size_t)BB * LL * 1024];
__device__ __align__(16) float g_y1[(size_t)BB * LL * 1024];
__device__ __align__(16) float g_ypart[(size_t)BB * TT * DMODEL];

// triangular tile map: 36 tiles (i<=j) in an 8x8 tile grid
__constant__ int c_TI[36] = {0,0,0,0,0,0,0,0, 1,1,1,1,1,1,1, 2,2,2,2,2,2,
                             3,3,3,3,3, 4,4,4,4, 5,5,5, 6,6, 7};
__constant__ int c_TJ[36] = {0,1,2,3,4,5,6,7, 1,2,3,4,5,6,7, 2,3,4,5,6,7,
                             3,4,5,6,7, 4,5,6,7, 5,6,7, 6,7, 7};

// ---------------- f32x2 packed-FMA helpers (sm_10x) ---------------------------
__device__ __forceinline__ unsigned long long pk2(float lo, float hi) {
    unsigned long long r;
    asm("mov.b64 %0, {%1, %2};" : "=l"(r) : "f"(lo), "f"(hi));
    return r;
}
__device__ __forceinline__ void upk2(unsigned long long v, float& lo, float& hi) {
    asm("mov.b64 {%0, %1}, %2;" : "=f"(lo), "=f"(hi) : "l"(v));
}
__device__ __forceinline__ void fma2(unsigned long long& d, unsigned long long a,
                                     unsigned long long b) {
    asm("fma.rn.f32x2 %0, %1, %2, %0;" : "+l"(d) : "l"(a), "l"(b));
}

// =============================================================================
// Kernel 1: R11 version (measured 321.5us at the 590us baseline).
// =============================================================================
__device__ __forceinline__ void k1_load_chunk(
    float* __restrict__ sm1, const float* __restrict__ qp,
    const float* __restrict__ kp, int b, int l, int chunk, int tid)
{
    #pragma unroll
    for (int g = 0; g < 4; g++) {
        int c = chunk * 4 + g;
        const float* src = (c < HH) ? qp : kp;
        int h = c % HH;
        const float* base = src + ((size_t)b * TT * 197 + (l + 1)) * DMODEL + h * DD;
        #pragma unroll
        for (int j = 0; j < 8; j++) {
            int idx = tid + j * 256;
            int t = idx >> 6, d = idx & 63;
            sm1[g * XS_HSTR + d * 34 + t] =
                base[(size_t)t * 197 * DMODEL + d] * 0.35355339059327376f;
        }
    }
}

__global__ __launch_bounds__(256) void k1_gram(
    const float* __restrict__ qp, const float* __restrict__ kp,
    const float* __restrict__ tw, const float* __restrict__ tb)
{
    extern __shared__ __align__(16) float dsm[];
    float* sm1 = dsm;
    float* gm  = dsm + XS_FLOATS;

    const int tid = threadIdx.x;
    const int bl = blockIdx.x;
    const int b = bl / LL, l = bl % LL;

    const bool gact = (tid < 144);
    const int gj = gact ? (tid / 36) : 0;
    const int tt = gact ? (tid - gj * 36) : 0;
    const int ti = gact ? c_TI[tt] : 0;
    const int tj = gact ? c_TJ[tt] : 0;
    const int q0 = ti * 4, k0 = tj * 4;

    const int ct1 = tid >> 3, ct2 = (tid & 7) * 4;
    const int lc = tid & 7;

    float racc[4] = {0.f, 0.f, 0.f, 0.f};

    k1_load_chunk(sm1, qp, kp, b, l, 0, tid);

    for (int chunk = 0; chunk < 6; chunk++) {
        __syncthreads();

        {
            unsigned long long acc[4][2] = {{0ull,0ull},{0ull,0ull},{0ull,0ull},{0ull,0ull}};
            if (gact) {
                const float* xg = sm1 + gj * XS_HSTR;
                #pragma unroll 4
                for (int d = 0; d < 64; d++) {
                    const float* row = xg + d * 34;
                    unsigned long long qa = *(const unsigned long long*)(row + q0);
                    unsigned long long qb = *(const unsigned long long*)(row + q0 + 2);
                    unsigned long long kk0 = *(const unsigned long long*)(row + k0);
                    unsigned long long kk1 = *(const unsigned long long*)(row + k0 + 2);
                    float q0v, q1v, q2v, q3v;
                    upk2(qa, q0v, q1v); upk2(qb, q2v, q3v);
                    unsigned long long p0 = pk2(q0v, q0v), p1 = pk2(q1v, q1v);
                    unsigned long long p2 = pk2(q2v, q2v), p3 = pk2(q3v, q3v);
                    fma2(acc[0][0], p0, kk0); fma2(acc[0][1], p0, kk1);
                    fma2(acc[1][0], p1, kk0); fma2(acc[1][1], p1, kk1);
                    fma2(acc[2][0], p2, kk0); fma2(acc[2][1], p2, kk1);
                    fma2(acc[3][0], p3, kk0); fma2(acc[3][1], p3, kk1);
                }
                float* gmg = gm + gj * GMH;
                #pragma unroll
                for (int r = 0; r < 4; r++) {
                    *(unsigned long long*)&gmg[(q0 + r) * GMS + k0]     = acc[r][0];
                    *(unsigned long long*)&gmg[(q0 + r) * GMS + k0 + 2] = acc[r][1];
                }
                if (ti != tj) {
                    float av[4][4];
                    #pragma unroll
                    for (int r = 0; r < 4; r++) {
                        upk2(acc[r][0], av[r][0], av[r][1]);
                        upk2(acc[r][1], av[r][2], av[r][3]);
                    }
                    #pragma unroll
                    for (int c = 0; c < 4; c++)
                        #pragma unroll
                        for (int r = 0; r < 4; r++)
                            gmg[(k0 + c) * GMS + q0 + r] = av[r][c];
                }
            }
        }
        __syncthreads();

        if (chunk + 1 < 6) k1_load_chunk(sm1, qp, kp, b, l, chunk + 1, tid);

        {
            int r = tid >> 1, h = tid & 1;
            float* row = gm + (r >> 5) * GMH + (r & 31) * GMS + h * 16;
            float4 v[4];
            #pragma unroll
            for (int j = 0; j < 4; j++) v[j] = *(const float4*)&row[j * 4];
            float mx = -1e30f;
            #pragma unroll
            for (int j = 0; j < 4; j++)
                mx = fmaxf(mx, fmaxf(fmaxf(v[j].x, v[j].y), fmaxf(v[j].z, v[j].w)));
            mx = fmaxf(mx, __shfl_xor_sync(0xffffffffu, mx, 1));
            float sum = 0.f;
            #pragma unroll
            for (int j = 0; j < 4; j++) {
                v[j].x = __expf(v[j].x - mx); v[j].y = __expf(v[j].y - mx);
                v[j].z = __expf(v[j].z - mx); v[j].w = __expf(v[j].w - mx);
                sum += (v[j].x + v[j].y) + (v[j].z + v[j].w);
            }
            sum += __shfl_xor_sync(0xffffffffu, sum, 1);
            float inv = __fdividef(1.f, sum);
            #pragma unroll
            for (int j = 0; j < 4; j++) {
                v[j].x *= inv; v[j].y *= inv; v[j].z *= inv; v[j].w *= inv;
                *(float4*)&row[j * 4] = v[j];
            }
        }
        __syncthreads();

        {
            float wreg[4][9];
            #pragma unroll
            for (int g = 0; g < 4; g++)
                #pragma unroll
                for (int j = 0; j < 9; j++) wreg[g][j] = tw[(chunk * 4 + g) * 9 + j];
            #pragma unroll
            for (int g = 0; g < 4; g++) {
                const float* gg = gm + g * GMH;
                #pragma unroll
                for (int dy = 0; dy < 3; dy++) {
                    int y = ct1 + dy - 1;
                    bool vy = ((unsigned)y < 32u);
                    float4 mid = vy ? *(const float4*)&gg[y * GMS + ct2]
                                    : make_float4(0.f, 0.f, 0.f, 0.f);
                    float wl = __shfl_up_sync(0xffffffffu, mid.w, 1);
                    float wr = __shfl_down_sync(0xffffffffu, mid.x, 1);
                    if (lc == 0) wl = 0.f;
                    if (lc == 7) wr = 0.f;
                    float win[6] = {wl, mid.x, mid.y, mid.z, mid.w, wr};
                    #pragma unroll
                    for (int dx = 0; dx < 3; dx++) {
                        float wt = wreg[g][dy * 3 + dx];
                        #pragma unroll
                        for (int m = 0; m < 4; m++)
                            racc[m] = fmaf(win[m + dx], wt, racc[m]);
                    }
                }
            }
        }
    }

    float bias = tb[0];
    float4 o = make_float4(racc[0] + bias, racc[1] + bias, racc[2] + bias, racc[3] + bias);
    *(float4*)&g_aff0[(size_t)bl * 1024 + ct1 * 32 + ct2] = o;
}

// =============================================================================
// Kernel 2: LN + MLP + residual, 8 rows per block.
// =============================================================================
__global__ __launch_bounds__(256) void k2_mlp(
    const float* __restrict__ lng, const float* __restrict__ lnb,
    const float* __restrict__ w1, const float* __restrict__ b1,
    const float* __restrict__ w2, const float* __restrict__ b2)
{
    __shared__ __align__(16) float xnT[1024 * 8];
    __shared__ float part[8 * 256];
    __shared__ float hs[256];
    __shared__ float mu[8], rs[8];

    const int tid = threadIdx.x;
    const int warp = tid >> 5, lane = tid & 31;
    const size_t R0 = (size_t)blockIdx.x * 8;

    {
        const float* xrow = g_aff0 + (R0 + warp) * 1024;
        float s1 = 0.f, s2 = 0.f;
        #pragma unroll 8
        for (int kk = 0; kk < 32; kk++) {
            float v = xrow[lane + 32 * kk];
            s1 += v; s2 += v * v;
        }
        #pragma unroll
        for (int o = 16; o > 0; o >>= 1) {
            s1 += __shfl_xor_sync(0xffffffffu, s1, o);
            s2 += __shfl_xor_sync(0xffffffffu, s2, o);
        }
        if (lane == 0) {
            float m = s1 * (1.f / 1024.f);
            float var = s2 * (1.f / 1024.f) - m * m;
            mu[warp] = m;
            rs[warp] = rsqrtf(var + 1e-5f);
        }
    }
    __syncthreads();

    for (int idx = tid; idx < 8192; idx += 256) {
        int r = idx >> 10, i = idx & 1023;
        float v = g_aff0[(R0 + r) * 1024 + i];
        xnT[i * 8 + r] = (v - mu[r]) * rs[r] * lng[i] + lnb[i];
    }
    __syncthreads();

    {
        unsigned long long acc[4] = {0ull, 0ull, 0ull, 0ull};
        int i0 = warp * 128;
        #pragma unroll 4
        for (int i = i0; i < i0 + 128; i++) {
            float wv = w1[i * 32 + lane];
            unsigned long long wp = pk2(wv, wv);
            const unsigned long long* xp = (const unsigned long long*)&xnT[i * 8];
            fma2(acc[0], wp, xp[0]);
            fma2(acc[1], wp, xp[1]);
            fma2(acc[2], wp, xp[2]);
            fma2(acc[3], wp, xp[3]);
        }
        #pragma unroll
        for (int rp = 0; rp < 4; rp++) {
            float a, bv; upk2(acc[rp], a, bv);
            part[warp * 256 + (2 * rp) * 32 + lane] = a;
            part[warp * 256 + (2 * rp + 1) * 32 + lane] = bv;
        }
    }
    __syncthreads();

    {
        float h = b1[lane];
        #pragma unroll
        for (int w = 0; w < 8; w++) h += part[w * 256 + warp * 32 + lane];
        hs[warp * 32 + lane] = 0.5f * h * (1.0f + erff(h * 0.70710678118654752f));
    }
    __syncthreads();

    #pragma unroll
    for (int u = 0; u < 4; u++) {
        int i = tid + u * 256;
        float acc[8];
        #pragma unroll
        for (int r = 0; r < 8; r++) acc[r] = g_aff0[(R0 + r) * 1024 + i];
        float bb = b2[i];
        #pragma unroll 8
        for (int j = 0; j < 32; j++) {
            float wv = w2[j * 1024 + i];
            #pragma unroll
            for (int r = 0; r < 8; r++) acc[r] = fmaf(hs[r * 32 + j], wv, acc[r]);
        }
        #pragma unroll
        for (int r = 0; r < 8; r++) g_y1[(R0 + r) * 1024 + i] = acc[r] + bb;
    }
}

// =============================================================================
// Kernel 3: p_conv 1024ch -> 1.
// =============================================================================
__global__ __launch_bounds__(256) void k3_pconv(
    const float* __restrict__ pw, const float* __restrict__ pb,
    float* __restrict__ out)
{
    __shared__ float red[8];
    const int tid = threadIdx.x;
    const int bi = blockIdx.x;
    const int b = bi / LL, l = bi % LL;
    const int p1 = l / PP, p2 = l % PP;
    const int ch = tid * 4;

    float wreg[9][4];
    #pragma unroll
    for (int tap = 0; tap < 9; tap++)
        #pragma unroll
        for (int m = 0; m < 4; m++) wreg[tap][m] = pw[(ch + m) * 9 + tap];

    float4 a = make_float4(0.f, 0.f, 0.f, 0.f);
    #pragma unroll
    for (int dy = 0; dy < 3; dy++) {
        int y = p1 + dy - 1;
        if ((unsigned)y >= (unsigned)PP) continue;
        #pragma unroll
        for (int dx = 0; dx < 3; dx++) {
            int x = p2 + dx - 1;
            if ((unsigned)x >= (unsigned)PP) continue;
            const float4 row = *(const float4*)&g_y1[((size_t)b * LL + y * PP + x) * 1024 + ch];
            int tap = dy * 3 + dx;
            a.x = fmaf(row.x, wreg[tap][0], a.x);
            a.y = fmaf(row.y, wreg[tap][1], a.y);
            a.z = fmaf(row.z, wreg[tap][2], a.z);
            a.w = fmaf(row.w, wreg[tap][3], a.w);
        }
    }
    float s = a.x + a.y + a.z + a.w;
    #pragma unroll
    for (int o = 16; o > 0; o >>= 1) s += __shfl_xor_sync(0xffffffffu, s, o);
    if ((tid & 31) == 0) red[tid >> 5] = s;
    __syncthreads();
    if (tid == 0) {
        float t = pb[0];
        #pragma unroll
        for (int w = 0; w < 8; w++) t += red[w];
        out[bi] = t;
    }
}

// =============================================================================
// Kernel 4: spatial syno attention (R9 form).
// =============================================================================
__global__ __launch_bounds__(256) void k4_spatial(
    const float* __restrict__ kp, const float* __restrict__ vp,
    const float* __restrict__ syno)
{
    __shared__ __align__(16) float buf[32 * 256];
    __shared__ __align__(16) float sc[16 * 200];
    __shared__ __align__(16) float syT[32 * 16];
    __shared__ float Pb[196];

    const int tid = threadIdx.x;
    const int bt = blockIdx.x;
    const float* kbase = kp + ((size_t)bt * 197 + 1) * DMODEL;
    const float* vbase = vp + ((size_t)bt * 197 + 1) * DMODEL;
    const float scale = 0.03608439182435161f;

    const int sg = tid / 49;
    const int lg = tid % 49;
    const bool act = (tid < 196);

    unsigned long long acc[4][2] = {{0ull,0ull},{0ull,0ull},{0ull,0ull},{0ull,0ull}};

    for (int dc = 0; dc < 24; dc++) {
        int d0 = dc * 32;
        if (tid < 128) {
            int s = tid >> 3, dq = tid & 7;
            float4 sv = *(const float4*)&syno[s * DMODEL + d0 + dq * 4];
            int base = 4 * ((s >> 2) ^ (dq & 3)) + (s & 3);
            syT[(dq * 4 + 0) * 16 + base] = sv.x * scale;
            syT[(dq * 4 + 1) * 16 + base] = sv.y * scale;
            syT[(dq * 4 + 2) * 16 + base] = sv.z * scale;
            syT[(dq * 4 + 3) * 16 + base] = sv.w * scale;
        }
        for (int idx = tid; idx < 1568; idx += 256) {
            int l = idx >> 3, kq = idx & 7;
            float4 kv = *(const float4*)&kbase[(size_t)l * DMODEL + d0 + kq * 4];
            int base = 4 * ((l >> 2) ^ kq) + (l & 3);
            buf[(kq * 4 + 0) * 256 + base] = kv.x;
            buf[(kq * 4 + 1) * 256 + base] = kv.y;
            buf[(kq * 4 + 2) * 256 + base] = kv.z;
            buf[(kq * 4 + 3) * 256 + base] = kv.w;
        }
        __syncthreads();
        if (act) {
            #pragma unroll 4
            for (int dd = 0; dd < 32; dd++) {
                float4 sa = *(const float4*)&syT[dd * 16 + 4 * (sg ^ ((dd >> 2) & 3))];
                float4 ka = *(const float4*)&buf[dd * 256 + 4 * (lg ^ ((dd >> 2) & 7))];
                unsigned long long k01 = pk2(ka.x, ka.y), k23 = pk2(ka.z, ka.w);
                unsigned long long s0 = pk2(sa.x, sa.x), s1 = pk2(sa.y, sa.y);
                unsigned long long s2 = pk2(sa.z, sa.z), s3 = pk2(sa.w, sa.w);
                fma2(acc[0][0], s0, k01); fma2(acc[0][1], s0, k23);
                fma2(acc[1][0], s1, k01); fma2(acc[1][1], s1, k23);
                fma2(acc[2][0], s2, k01); fma2(acc[2][1], s2, k23);
                fma2(acc[3][0], s3, k01); fma2(acc[3][1], s3, k23);
            }
        }
        __syncthreads();
    }
    if (act) {
        #pragma unroll
        for (int i = 0; i < 4; i++) {
            *(unsigned long long*)&sc[(sg * 4 + i) * 200 + lg * 4]     = acc[i][0];
            *(unsigned long long*)&sc[(sg * 4 + i) * 200 + lg * 4 + 2] = acc[i][1];
        }
    }
    __syncthreads();

    const int warp = tid >> 5, lane = tid & 31;
    #pragma unroll
    for (int si = 0; si < 2; si++) {
        int s = warp * 2 + si;
        float mx = -1e30f;
        for (int li = lane; li < 196; li += 32) mx = fmaxf(mx, sc[s * 200 + li]);
        #pragma unroll
        for (int o = 16; o > 0; o >>= 1) mx = fmaxf(mx, __shfl_xor_sync(0xffffffffu, mx, o));
        float sum = 0.f;
        for (int li = lane; li < 196; li += 32) {
            float e = __expf(sc[s * 200 + li] - mx);
            sc[s * 200 + li] = e; sum += e;
        }
        #pragma unroll
        for (int o = 16; o > 0; o >>= 1) sum += __shfl_xor_sync(0xffffffffu, sum, o);
        float inv = __fdividef(1.f, sum);
        for (int li = lane; li < 196; li += 32) sc[s * 200 + li] *= inv;
    }
    __syncthreads();

    if (tid < 196) {
        float p = 0.f;
        #pragma unroll
        for (int s = 0; s < 16; s++) p += sc[s * 200 + tid];
        Pb[tid] = p;
    }
    __syncthreads();

    if (tid < 192) {
        int w4 = tid * 4;
        float ax = 0.f, ay = 0.f, az = 0.f, aw = 0.f;
        for (int l = 0; l < 196; l += 4) {
            #pragma unroll
            for (int u = 0; u < 4; u++) {
                float p = Pb[l + u];
                float4 vv = *(const float4*)&vbase[(size_t)(l + u) * DMODEL + w4];
                ax = fmaf(p, vv.x, ax);
                ay = fmaf(p, vv.y, ay);
                az = fmaf(p, vv.z, az);
                aw = fmaf(p, vv.w, aw);
            }
        }
        *(float4*)&g_ypart[(size_t)bt * DMODEL + w4] = make_float4(ax, ay, az, aw);
    }
}

// =============================================================================
// Kernel 5: y_s[b][w] = sum_t partial / 512
// =============================================================================
__global__ __launch_bounds__(768) void k5_reduce(float* __restrict__ out)
{
    const int b = blockIdx.x, w = threadIdx.x;
    float s = 0.f;
    #pragma unroll
    for (int t = 0; t < 32; t++) s += g_ypart[((size_t)b * 32 + t) * DMODEL + w];
    out[b * DMODEL + w] = s * (1.f / 512.f);
}

// =============================================================================
extern "C" void kernel_launch(void* const* d_in, const int* in_sizes, int n_in,
                              void* d_out, int out_size)
{
    const float* q    = (const float*)d_in[0];
    const float* k    = (const float*)d_in[1];
    const float* v    = (const float*)d_in[2];
    const float* tw   = (const float*)d_in[3];
    const float* tb   = (const float*)d_in[4];
    const float* lng  = (const float*)d_in[5];
    const float* lnb  = (const float*)d_in[6];
    const float* w1   = (const float*)d_in[7];
    const float* b1   = (const float*)d_in[8];
    const float* w2   = (const float*)d_in[9];
    const float* b2   = (const float*)d_in[10];
    const float* pw   = (const float*)d_in[11];
    const float* pb   = (const float*)d_in[12];
    const float* syno = (const float*)d_in[13];
    float* out = (float*)d_out;

    static int s_attr_done = 0;
    if (!s_attr_done) {
        cudaFuncSetAttribute(k1_gram, cudaFuncAttributeMaxDynamicSharedMemorySize,
                             K1_SMEM);
        s_attr_done = 1;
    }

    k1_gram<<<BB * LL, 256, K1_SMEM>>>(q, k, tw, tb);
    k2_mlp<<<BB * LL / 8, 256>>>(lng, lnb, w1, b1, w2, b2);
    k3_pconv<<<BB * LL, 256>>>(pw, pb, out);
    k4_spatial<<<BB * TT, 256>>>(k, v, syno);
    k5_reduce<<<BB, 768>>>(out + BB * LL);
}